// round 7
// baseline (speedup 1.0000x reference)
#include <cuda_runtime.h>
#include <cstdint>

#define T_LEN 2048
#define F_DIM 32
#define B_TOT 512
#define NB    4                        // batches per CTA (= per warp, ILP)

typedef unsigned long long U;          // packed f32x2 carrier

// ---------------- packed fp32x2 helpers ------------------------------------
__device__ __forceinline__ U ffma2(U a, U b, U c) {
    U d; asm("fma.rn.f32x2 %0, %1, %2, %3;" : "=l"(d) : "l"(a), "l"(b), "l"(c));
    return d;
}
__device__ __forceinline__ U pack2(float lo, float hi) {
    U d; asm("mov.b64 %0, {%1, %2};" : "=l"(d) : "f"(lo), "f"(hi));
    return d;
}
__device__ __forceinline__ float2 unpk(U d) {
    float2 r; asm("mov.b64 {%0, %1}, %2;" : "=f"(r.x), "=f"(r.y) : "l"(d));
    return r;
}

// ---------------- activations (proven 1.4e-7 end-to-end) --------------------
__device__ __forceinline__ float sig_a(float x) {
    float e = __expf(-x);
    return __fdividef(1.0f, 1.0f + e);
}
__device__ __forceinline__ float tanh_a(float x) {
    x = fminf(15.0f, fmaxf(-15.0f, x));
    float e = __expf(-2.0f * x);
    return __fdividef(1.0f - e, 1.0f + e);
}

// ============================================================================
// Fully fused LSTM + output linear, 4-batch ILP per warp.
//   grid = 128 (1 CTA/SM), CTA = 4 warps (warp = gate), 4 batches per CTA.
//   Phase 1: warp w computes gate w + out-linear chunk w for ALL 4 batches.
//   Phase 2: warp w owns batch w: c/h update, z staging, out finish, x ring.
//   Exchange: gp[gate][batch][f] = float2(activation, out_partial).
// ============================================================================
__global__ void __launch_bounds__(128, 1)
lstm_fused(const float* __restrict__ x,
           const float* __restrict__ W_ih,
           const float* __restrict__ W_hh,
           const float* __restrict__ b_ih,
           const float* __restrict__ b_hh,
           const float* __restrict__ W_lin,
           const float* __restrict__ b_lin,
           float* __restrict__ out)
{
    __shared__ __align__(16) float  zb[NB][2][2 * F_DIM];   // (h_j, x_j) interleaved
    __shared__ __align__(16) float2 gp[4][NB][F_DIM];       // (act, out_partial)

    const int w = threadIdx.x >> 5;    // warp = gate (0..3) and owned batch
    const int f = threadIdx.x & 31;    // lane = feature
    const int b0 = blockIdx.x * NB;    // first batch of this CTA

    // ---- gate weights: pair j = (W_hh[w,f,j], W_ih[w,f,j]) ----
    U wc[32];
    {
        const float* ph = W_hh + (size_t)(w * F_DIM + f) * F_DIM;
        const float* pi = W_ih + (size_t)(w * F_DIM + f) * F_DIM;
#pragma unroll
        for (int j = 0; j < 32; j++) wc[j] = pack2(ph[j], pi[j]);
    }
    const float bias = b_ih[w * F_DIM + f] + b_hh[w * F_DIM + f];

    // ---- out-linear chunk: pairs 8w .. 8w+7 ----
    U wl[8];
    {
        const float* pl = W_lin + (size_t)f * 2 * F_DIM + w * 16;
#pragma unroll
        for (int m = 0; m < 8; m++) wl[m] = pack2(pl[2 * m], pl[2 * m + 1]);
    }
    const float ob = b_lin[f];

    // own batch (= w) pointers for phase 2
    const float* xp = x   + (size_t)(b0 + w) * T_LEN * F_DIM + f;
    float*       op = out + (size_t)(b0 + w) * T_LEN * F_DIM + f;

    float c = 0.0f;             // own batch cell state
    float prev_sx[NB];          // per-batch carried x-part of out partial
    float xr[4];                // own batch x prefetch ring (x_{t+1..t+4})

#pragma unroll
    for (int p = 0; p < NB; p++) prev_sx[p] = 0.0f;

    // stage z[own][0] = (h_{-1}=0, x_0); fill ring
    *(float2*)&zb[w][0][2 * f] = make_float2(0.0f, xp[0]);
#pragma unroll
    for (int k = 0; k < 4; k++) xr[k] = xp[(size_t)(k + 1) * F_DIM];
    __syncthreads();

    for (int tb = 0; tb < T_LEN; tb += 4) {
#pragma unroll
        for (int u = 0; u < 4; u++) {
            const int t  = tb + u;
            const int s  = u & 1;
            const int ns = s ^ 1;

            // ---------- phase 1: gate + out-chunk for all 4 batches ----------
#pragma unroll
            for (int p = 0; p < NB; p++) {
                const ulonglong2* zr = (const ulonglong2*)&zb[p][s][0];  // uniform
                U a0 = pack2(bias, 0.f), a1 = pack2(0.f, 0.f);
                U a2 = pack2(0.f, 0.f),  a3 = pack2(0.f, 0.f);
#pragma unroll
                for (int q = 0; q < 16; q += 2) {
                    ulonglong2 v0 = zr[q];
                    ulonglong2 v1 = zr[q + 1];
                    a0 = ffma2(wc[2 * q],     v0.x, a0);
                    a1 = ffma2(wc[2 * q + 1], v0.y, a1);
                    a2 = ffma2(wc[2 * q + 2], v1.x, a2);
                    a3 = ffma2(wc[2 * q + 3], v1.y, a3);
                }
                U o0 = pack2(0.f, 0.f), o1 = pack2(0.f, 0.f);
#pragma unroll
                for (int m = 0; m < 4; m++) {
                    ulonglong2 v = zr[4 * w + m];
                    o0 = ffma2(wl[2 * m],     v.x, o0);
                    o1 = ffma2(wl[2 * m + 1], v.y, o1);
                }
                float2 u0 = unpk(a0), u1 = unpk(a1), u2 = unpk(a2), u3 = unpk(a3);
                float pre = ((u0.x + u0.y) + (u1.x + u1.y))
                          + ((u2.x + u2.y) + (u3.x + u3.y));
                float act = (w == 2) ? tanh_a(pre) : sig_a(pre);

                float2 s0 = unpk(o0), s1 = unpk(o1);
                float part = (s0.x + s1.x) + prev_sx[p];   // h(t-1)+x(t-1) parts
                prev_sx[p] = s0.y + s1.y;                  // carry x(t) part
                gp[w][p][f] = make_float2(act, part);
            }

            __syncthreads();   // BAR1: all acts + partials published

            // ---------- phase 2: own batch (= w) ----------
            {
                float2 q0 = gp[0][w][f];
                float2 q1 = gp[1][w][f];
                float2 q2 = gp[2][w][f];
                float2 q3 = gp[3][w][f];
                c = q1.x * c + q0.x * q2.x;              // f*c + i*g
                float h = q3.x * tanh_a(c);              // o * tanh(c)
                *(float2*)&zb[w][ns][2 * f] = make_float2(h, xr[u]);  // (h_t, x_{t+1})
                int pt = t + 5; if (pt > T_LEN - 1) pt = T_LEN - 1;
                xr[u] = xp[(size_t)pt * F_DIM];
                if (t > 0)
                    op[(size_t)(t - 1) * F_DIM] =
                        tanh_a(q0.y + q1.y + q2.y + q3.y + ob);
            }

            __syncthreads();   // BAR2: zb[ns] published
        }
    }

    // ---- epilogue: out_{T-1}. zb[p][0] = (h_{T-1}, junk); only .x used ----
#pragma unroll
    for (int p = 0; p < NB; p++) {
        const ulonglong2* zr = (const ulonglong2*)&zb[p][0][0];
        U o0 = pack2(0.f, 0.f), o1 = pack2(0.f, 0.f);
#pragma unroll
        for (int m = 0; m < 4; m++) {
            ulonglong2 v = zr[4 * w + m];
            o0 = ffma2(wl[2 * m],     v.x, o0);
            o1 = ffma2(wl[2 * m + 1], v.y, o1);
        }
        float2 s0 = unpk(o0), s1 = unpk(o1);
        gp[w][p][f] = make_float2(0.0f, (s0.x + s1.x) + prev_sx[p]);
    }
    __syncthreads();
    {
        float sum = gp[0][w][f].y + gp[1][w][f].y + gp[2][w][f].y
                  + gp[3][w][f].y + ob;
        op[(size_t)(T_LEN - 1) * F_DIM] = tanh_a(sum);
    }
}

// ============================================================================
extern "C" void kernel_launch(void* const* d_in, const int* in_sizes, int n_in,
                              void* d_out, int out_size)
{
    const float* x     = (const float*)d_in[0];
    const float* W_ih  = (const float*)d_in[1];
    const float* W_hh  = (const float*)d_in[2];
    const float* b_ih  = (const float*)d_in[3];
    const float* b_hh  = (const float*)d_in[4];
    const float* W_lin = (const float*)d_in[5];
    const float* b_lin = (const float*)d_in[6];
    float* out = (float*)d_out;

    lstm_fused<<<B_TOT / NB, 128>>>(x, W_ih, W_hh, b_ih, b_hh, W_lin, b_lin, out);
}

// round 8
// speedup vs baseline: 1.5195x; 1.5195x over previous
#include <cuda_runtime.h>
#include <cstdint>

#define T_LEN 2048
#define F_DIM 32
#define B_TOT 512

typedef unsigned long long U;          // packed f32x2 carrier

// ---------------- packed fp32x2 helpers ------------------------------------
__device__ __forceinline__ U ffma2(U a, U b, U c) {
    U d; asm("fma.rn.f32x2 %0, %1, %2, %3;" : "=l"(d) : "l"(a), "l"(b), "l"(c));
    return d;
}
__device__ __forceinline__ U add2(U a, U b) {
    U d; asm("add.rn.f32x2 %0, %1, %2;" : "=l"(d) : "l"(a), "l"(b));
    return d;
}
__device__ __forceinline__ U pack2(float lo, float hi) {
    U d; asm("mov.b64 %0, {%1, %2};" : "=l"(d) : "f"(lo), "f"(hi));
    return d;
}
__device__ __forceinline__ float2 unpk(U d) {
    float2 r; asm("mov.b64 {%0, %1}, %2;" : "=f"(r.x), "=f"(r.y) : "l"(d));
    return r;
}

// ---------------- activations (proven 1.4e-7 end-to-end) --------------------
__device__ __forceinline__ float sig_a(float x) {
    float e = __expf(-x);
    return __fdividef(1.0f, 1.0f + e);
}
__device__ __forceinline__ float tanh_a(float x) {
    x = fminf(15.0f, fmaxf(-15.0f, x));
    float e = __expf(-2.0f * x);
    return __fdividef(1.0f - e, 1.0f + e);
}

// ============================================================================
// Fused LSTM + out-linear. CTA = 1 batch, 4 warps (warp = gate), 4 CTAs/SM.
// ONE __syncthreads per step (gate exchange). Every warp redundantly computes
// c/h -> h lives in smem written by each warp itself (syncwarp visibility).
// x-dependent dot parts computed in the post-barrier shadow and carried.
// ============================================================================
__global__ void __launch_bounds__(128, 4)
lstm_fused(const float* __restrict__ x,
           const float* __restrict__ W_ih,
           const float* __restrict__ W_hh,
           const float* __restrict__ b_ih,
           const float* __restrict__ b_hh,
           const float* __restrict__ W_lin,
           const float* __restrict__ b_lin,
           float* __restrict__ out)
{
    __shared__ __align__(16) float  hb[F_DIM];        // h_{t-1} (single buffer)
    __shared__ __align__(16) float  xb[2][F_DIM];     // x_t / x_{t+1} (parity t&1)
    __shared__ __align__(16) float2 gp[2][4][F_DIM];  // (act, out_partial), parity

    const int w = threadIdx.x >> 5;    // warp = gate (0..3)
    const int f = threadIdx.x & 31;    // lane = feature
    const int b = blockIdx.x;          // batch

    // ---- gate weights split: whh pairs vs wih pairs ----
    U whh[16], wih[16];
    {
        const U* ph = (const U*)(W_hh + (size_t)(w * F_DIM + f) * F_DIM);
        const U* pi = (const U*)(W_ih + (size_t)(w * F_DIM + f) * F_DIM);
#pragma unroll
        for (int k = 0; k < 16; k++) { whh[k] = ph[k]; wih[k] = pi[k]; }
    }
    const float bias = b_ih[w * F_DIM + f] + b_hh[w * F_DIM + f];

    // ---- out-linear chunk (pair-halves m = 4w..4w+3) ----
    //   h weights: (W[f][4m], W[f][4m+2]);  x weights: (W[f][4m+1], W[f][4m+3])
    U whO[4], whX[4];
    {
        const float* pl = W_lin + (size_t)f * 2 * F_DIM;
#pragma unroll
        for (int mm = 0; mm < 4; mm++) {
            int m4 = 4 * (4 * w + mm);
            whO[mm] = pack2(pl[m4],     pl[m4 + 2]);
            whX[mm] = pack2(pl[m4 + 1], pl[m4 + 3]);
        }
    }
    const float ob = b_lin[f];
    const U ZERO = pack2(0.0f, 0.0f);

    const float* xp = x   + (size_t)b * T_LEN * F_DIM + f;
    float*       op = out + (size_t)b * T_LEN * F_DIM + f;

    float c = 0.0f;
    float xr[4];                 // x ring: x_{t+1..t+4}
    U xacc0, xacc1;              // bias + W_ih · x_t (packed carry)
    U ox0 = ZERO, ox1 = ZERO;    // W_odd · x_{t-1} chunk (packed carry)

    // ---- preamble: h_{-1}=0, stage x_0, ring x_1..x_4, xacc(x_0) ----
    hb[f] = 0.0f;
    xb[0][f] = xp[0];
#pragma unroll
    for (int k = 0; k < 4; k++) xr[k] = xp[(size_t)(k + 1) * F_DIM];
    __syncthreads();
    {
        const ulonglong2* xz = (const ulonglong2*)&xb[0][0];
        xacc0 = pack2(bias, 0.0f); xacc1 = ZERO;
#pragma unroll
        for (int i = 0; i < 8; i++) {
            ulonglong2 v = xz[i];
            xacc0 = ffma2(wih[2 * i],     v.x, xacc0);
            xacc1 = ffma2(wih[2 * i + 1], v.y, xacc1);
        }
    }

    for (int tb = 0; tb < T_LEN; tb += 4) {
#pragma unroll
        for (int u = 0; u < 4; u++) {
            const int t  = tb + u;
            const int s  = u & 1;
            const int ns = s ^ 1;

            // ========== phase 1 (critical): h-dot + act + out-h chunk ======
            const ulonglong2* hz = (const ulonglong2*)&hb[0];
            U a0 = xacc0, a1 = xacc1;
#pragma unroll
            for (int i = 0; i < 8; i++) {
                ulonglong2 v = hz[i];
                a0 = ffma2(whh[2 * i],     v.x, a0);
                a1 = ffma2(whh[2 * i + 1], v.y, a1);
            }
            ulonglong2 h0 = hz[2 * w];
            ulonglong2 h1 = hz[2 * w + 1];
            U p0 = ffma2(whO[0], h0.x, ox0);
            U p1 = ffma2(whO[1], h0.y, ox1);
            p0 = ffma2(whO[2], h1.x, p0);
            p1 = ffma2(whO[3], h1.y, p1);

            float2 gs = unpk(add2(a0, a1));
            float pre = gs.x + gs.y;
            float act = (w == 2) ? tanh_a(pre) : sig_a(pre);
            float2 ps = unpk(add2(p0, p1));
            gp[s][w][f] = make_float2(act, ps.x + ps.y);   // part of out_{t-1}

            __syncthreads();   // the ONLY barrier per step

            // ========== phase 2 (shadow): redundant c/h, staging, x-dots ===
            float2 q0 = gp[s][0][f];
            float2 q1 = gp[s][1][f];
            float2 q2 = gp[s][2][f];
            float2 q3 = gp[s][3][f];
            c = q1.x * c + q0.x * q2.x;            // f*c + i*g
            float h = q3.x * tanh_a(c);            // o * tanh(c)
            hb[f] = h;                             // every warp writes (identical)
            xb[ns][f] = xr[u];                     // stage x_{t+1}

            if (w == (t & 3) && t > 0)
                op[(size_t)(t - 1) * F_DIM] =
                    tanh_a(q0.y + q1.y + q2.y + q3.y + ob);

            int pt = t + 5; if (pt > T_LEN - 1) pt = T_LEN - 1;
            xr[u] = xp[(size_t)pt * F_DIM];        // refill ring

            // out-x chunk over x_t (xb[s]) -> consumed next phase 1
            {
                const ulonglong2* xzs = (const ulonglong2*)&xb[s][0];
                ulonglong2 x0 = xzs[2 * w];
                ulonglong2 x1 = xzs[2 * w + 1];
                ox0 = ffma2(whX[0], x0.x, ZERO);
                ox1 = ffma2(whX[1], x0.y, ZERO);
                ox0 = ffma2(whX[2], x1.x, ox0);
                ox1 = ffma2(whX[3], x1.y, ox1);
            }

            __syncwarp();      // own-warp hb/xb[ns] writes visible to own reads

            // gate x-dot over x_{t+1} (xb[ns]) -> xacc for next step
            {
                const ulonglong2* xz = (const ulonglong2*)&xb[ns][0];
                xacc0 = pack2(bias, 0.0f); xacc1 = ZERO;
#pragma unroll
                for (int i = 0; i < 8; i++) {
                    ulonglong2 v = xz[i];
                    xacc0 = ffma2(wih[2 * i],     v.x, xacc0);
                    xacc1 = ffma2(wih[2 * i + 1], v.y, xacc1);
                }
            }
        }
    }

    // ---- epilogue: out_{T-1} = Weven·h_{T-1} + ox(x_{T-1}) ----
    {
        const ulonglong2* hz = (const ulonglong2*)&hb[0];
        ulonglong2 h0 = hz[2 * w];
        ulonglong2 h1 = hz[2 * w + 1];
        U p0 = ffma2(whO[0], h0.x, ox0);
        U p1 = ffma2(whO[1], h0.y, ox1);
        p0 = ffma2(whO[2], h1.x, p0);
        p1 = ffma2(whO[3], h1.y, p1);
        float2 ps = unpk(add2(p0, p1));
        gp[0][w][f] = make_float2(0.0f, ps.x + ps.y);
        __syncthreads();
        if (w == 0) {
            float sum = gp[0][0][f].y + gp[0][1][f].y
                      + gp[0][2][f].y + gp[0][3][f].y + ob;
            op[(size_t)(T_LEN - 1) * F_DIM] = tanh_a(sum);
        }
    }
}

// ============================================================================
extern "C" void kernel_launch(void* const* d_in, const int* in_sizes, int n_in,
                              void* d_out, int out_size)
{
    const float* x     = (const float*)d_in[0];
    const float* W_ih  = (const float*)d_in[1];
    const float* W_hh  = (const float*)d_in[2];
    const float* b_ih  = (const float*)d_in[3];
    const float* b_hh  = (const float*)d_in[4];
    const float* W_lin = (const float*)d_in[5];
    const float* b_lin = (const float*)d_in[6];
    float* out = (float*)d_out;

    lstm_fused<<<B_TOT, 128>>>(x, W_ih, W_hh, b_ih, b_hh, W_lin, b_lin, out);
}